// round 1
// baseline (speedup 1.0000x reference)
#include <cuda_runtime.h>
#include <cstddef>

// Problem constants: x is [B=16, C=3, H=512, W=512] float32, patch=35, pad=17.
#define B 16
#define H 512
#define W 512
#define PATCH 35
#define HALO 17          // PATCH/2

// ---- vertical pass tiling ----
#define V_TH 64                      // output rows per tile
#define V_ROWS (V_TH + 2 * HALO)     // 98 loaded rows
// ---- horizontal pass tiling ----
#define H_TC 64                      // output cols per tile
#define H_CR 32                      // rows per tile
#define H_COLS (H_TC + 2 * HALO)     // 98 loaded cols
#define H_STRIDE 100                 // padded shared stride

#define NEG_BIG (-1e30f)

// Static scratch (no allocations allowed in kernel_launch).
__device__ float g_tmp[(size_t)B * H * W];           // 16 MB
__device__ float g_part[B * (H / H_CR) * (W / H_TC)]; // 2048 partials

// --------------------------------------------------------------------------
// Kernel 1: channel max of (1-x)  ==  1 - min_c(x), then vertical sliding
// max of window 35 via log-doubling in shared memory.
// Grid: (W/32, H/V_TH, B), Block: (32, 8)
// --------------------------------------------------------------------------
__global__ void vpass(const float* __restrict__ x, float* __restrict__ tmp) {
    __shared__ float sA[V_ROWS * 32];
    __shared__ float sB[V_ROWS * 32];

    const int tx = threadIdx.x;           // 0..31 -> column
    const int ty = threadIdx.y;           // 0..7
    const int b  = blockIdx.z;
    const int tileY = blockIdx.y;
    const int col   = blockIdx.x * 32 + tx;

    const float* xb = x + (size_t)b * 3 * H * W;
    const int r0 = tileY * V_TH;

    // Load 98 rows (with -inf padding outside [0,H)) and fuse channel min.
    #pragma unroll
    for (int i = ty; i < V_ROWS; i += 8) {
        int gr = r0 - HALO + i;
        float v;
        if (gr < 0 || gr >= H) {
            v = NEG_BIG;
        } else {
            size_t off = (size_t)gr * W + col;
            float c0 = xb[off];
            float c1 = xb[off + (size_t)H * W];
            float c2 = xb[off + 2 * (size_t)H * W];
            v = 1.0f - fminf(c0, fminf(c1, c2));
        }
        sA[i * 32 + tx] = v;
    }
    __syncthreads();

    // Doubling: after steps {1,2,4,8,16}, src[i] = max over [i, i+31].
    float* src = sA;
    float* dst = sB;
    int valid = V_ROWS;
    const int offs[5] = {1, 2, 4, 8, 16};
    #pragma unroll
    for (int k = 0; k < 5; k++) {
        int o = offs[k];
        valid -= o;
        for (int i = ty; i < valid; i += 8)
            dst[i * 32 + tx] = fmaxf(src[i * 32 + tx], src[(i + o) * 32 + tx]);
        __syncthreads();
        float* t = src; src = dst; dst = t;
    }
    // src = M32, valid indices [0, 67). Output j needs M32[j] and M32[j+3]:
    // window [r-17, r+14] U [r-14, r+17] = [r-17, r+17], exactly 35 wide.
    #pragma unroll
    for (int j = ty; j < V_TH; j += 8) {
        float v = fmaxf(src[j * 32 + tx], src[(j + 3) * 32 + tx]);
        tmp[((size_t)b * H + r0 + j) * W + col] = v;
    }
}

// --------------------------------------------------------------------------
// Kernel 2: horizontal sliding max (window 35) via doubling + block sum.
// Grid: (W/H_TC, H/H_CR, B), Block: (32, 8)
// --------------------------------------------------------------------------
__global__ void hpass(const float* __restrict__ tmp, float* __restrict__ part) {
    __shared__ float sA[H_CR * H_STRIDE];
    __shared__ float sB[H_CR * H_STRIDE];
    __shared__ float red[256];

    const int tx = threadIdx.x;
    const int ty = threadIdx.y;
    const int tid = ty * 32 + tx;
    const int b = blockIdx.z;
    const int rowTile = blockIdx.y;
    const int colTile = blockIdx.x;
    const int c0 = colTile * H_TC;

    // Load 32 rows x 98 cols with -inf padding for out-of-range columns.
    #pragma unroll
    for (int r = ty; r < H_CR; r += 8) {
        int gr = rowTile * H_CR + r;
        const float* rowp = tmp + ((size_t)b * H + gr) * W;
        #pragma unroll
        for (int c = tx; c < H_COLS; c += 32) {
            int gc = c0 - HALO + c;
            float v = (gc < 0 || gc >= W) ? NEG_BIG : rowp[gc];
            sA[r * H_STRIDE + c] = v;
        }
    }
    __syncthreads();

    float* src = sA;
    float* dst = sB;
    int valid = H_COLS;
    const int offs[5] = {1, 2, 4, 8, 16};
    #pragma unroll
    for (int k = 0; k < 5; k++) {
        int o = offs[k];
        valid -= o;
        for (int r = ty; r < H_CR; r += 8)
            for (int c = tx; c < valid; c += 32)
                dst[r * H_STRIDE + c] =
                    fmaxf(src[r * H_STRIDE + c], src[r * H_STRIDE + c + o]);
        __syncthreads();
        float* t = src; src = dst; dst = t;
    }

    // Final window combine + accumulate (dc >= 0, so |dc| = dc).
    float acc = 0.0f;
    #pragma unroll
    for (int r = ty; r < H_CR; r += 8)
        #pragma unroll
        for (int j = tx; j < H_TC; j += 32)
            acc += fmaxf(src[r * H_STRIDE + j], src[r * H_STRIDE + j + 3]);

    // Block tree reduction (deterministic).
    red[tid] = acc;
    __syncthreads();
    for (int s = 128; s > 0; s >>= 1) {
        if (tid < s) red[tid] += red[tid + s];
        __syncthreads();
    }
    if (tid == 0) {
        int bi = (b * gridDim.y + rowTile) * gridDim.x + colTile;
        part[bi] = red[0];
    }
}

// --------------------------------------------------------------------------
// Kernel 3: reduce 2048 partials in double, write -mean.
// --------------------------------------------------------------------------
__global__ void final_reduce(const float* __restrict__ part, float* __restrict__ out) {
    __shared__ double red[256];
    const int tid = threadIdx.x;
    const int NPART = B * (H / H_CR) * (W / H_TC);
    double acc = 0.0;
    for (int i = tid; i < NPART; i += 256) acc += (double)part[i];
    red[tid] = acc;
    __syncthreads();
    for (int s = 128; s > 0; s >>= 1) {
        if (tid < s) red[tid] += red[tid + s];
        __syncthreads();
    }
    if (tid == 0) {
        double n = (double)B * H * W;
        out[0] = (float)(-(red[0] / n));
    }
}

extern "C" void kernel_launch(void* const* d_in, const int* in_sizes, int n_in,
                              void* d_out, int out_size) {
    const float* x = (const float*)d_in[0];
    float* out = (float*)d_out;

    float* tmp;
    float* part;
    cudaGetSymbolAddress((void**)&tmp, g_tmp);
    cudaGetSymbolAddress((void**)&part, g_part);

    dim3 vblk(32, 8);
    dim3 vgrd(W / 32, H / V_TH, B);            // (16, 8, 16)
    vpass<<<vgrd, vblk>>>(x, tmp);

    dim3 hblk(32, 8);
    dim3 hgrd(W / H_TC, H / H_CR, B);          // (8, 16, 16)
    hpass<<<hgrd, hblk>>>(tmp, part);

    final_reduce<<<1, 256>>>(part, out);
}

// round 2
// speedup vs baseline: 1.3279x; 1.3279x over previous
#include <cuda_runtime.h>
#include <cstddef>

// x: [B=16, C=3, H=512, W=512] float32; patch=35, pad=17.
#define B 16
#define H 512
#define W 512
#define HALO 17

#define NEG_BIG (-1e30f)

// ---------------- vpass tiling ----------------
#define V_TH 64                       // output rows / tile
#define V_ROWS (V_TH + 2 * HALO)      // 98 loaded rows
#define V_C4 32                       // float4 cols / tile (=128 cols)
#define SV 132                        // shared row stride in floats (33 float4)
// shared: A = 98*132 floats, B = 95*132 floats

// ---------------- hpass tiling ----------------
#define H_TR 32                       // rows / tile
#define H_OC 128                      // output cols / tile
#define H_LC4 42                      // loaded float4 cols (168 cols, lb = c0-20)
#define SH 172                        // shared row stride in floats (43 float4)

__device__ float g_tmp[(size_t)B * H * W];
__device__ float g_part[B * (H / H_TR) * (W / H_OC)];   // 1024 partials

__device__ __forceinline__ float4 f4max(float4 a, float4 b) {
    return make_float4(fmaxf(a.x, b.x), fmaxf(a.y, b.y),
                       fmaxf(a.z, b.z), fmaxf(a.w, b.w));
}

// --------------------------------------------------------------------------
// vpass: channel max of (1-x) fused with vertical 35-window max.
// Grid (W/128, H/64, B) = (4,8,16), block 256. Dynamic smem ~99.5 KB.
// --------------------------------------------------------------------------
__global__ void vpass(const float* __restrict__ x, float* __restrict__ tmp) {
    extern __shared__ float smem[];
    float* sA = smem;                 // raw (98 rows) -> later M16v (80 rows)
    float* sB = smem + V_ROWS * SV;   // M4v (95 rows)

    const int tid = threadIdx.y * 32 + threadIdx.x;
    const int b   = blockIdx.z;
    const int r0  = blockIdx.y * V_TH;
    const int c0  = blockIdx.x * (V_C4 * 4);

    const float* xb = x + (size_t)b * 3 * H * W;

    // Phase L: load 98 rows x 32 float4, fused v = 1 - min_c(x).
    #pragma unroll 4
    for (int u = tid; u < V_ROWS * V_C4; u += 256) {
        const int i  = u >> 5;
        const int c4 = u & 31;
        const int gr = r0 - HALO + i;
        float4 v;
        if (gr >= 0 && gr < H) {
            const float* p = xb + (size_t)gr * W + c0 + 4 * c4;
            float4 a0 = *(const float4*)p;
            float4 a1 = *(const float4*)(p + (size_t)H * W);
            float4 a2 = *(const float4*)(p + 2 * (size_t)H * W);
            v.x = 1.0f - fminf(a0.x, fminf(a1.x, a2.x));
            v.y = 1.0f - fminf(a0.y, fminf(a1.y, a2.y));
            v.z = 1.0f - fminf(a0.z, fminf(a1.z, a2.z));
            v.w = 1.0f - fminf(a0.w, fminf(a1.w, a2.w));
        } else {
            v = make_float4(NEG_BIG, NEG_BIG, NEG_BIG, NEG_BIG);
        }
        *(float4*)(sA + i * SV + 4 * c4) = v;
    }
    __syncthreads();

    // Phase M4v: sB[i] = max(rows i..i+3), i in [0,95).
    #pragma unroll 4
    for (int u = tid; u < (V_ROWS - 3) * V_C4; u += 256) {
        const int i  = u >> 5;
        const int c4 = u & 31;
        float4 a = *(const float4*)(sA + (i    ) * SV + 4 * c4);
        float4 b1 = *(const float4*)(sA + (i + 1) * SV + 4 * c4);
        float4 c = *(const float4*)(sA + (i + 2) * SV + 4 * c4);
        float4 d = *(const float4*)(sA + (i + 3) * SV + 4 * c4);
        *(float4*)(sB + i * SV + 4 * c4) = f4max(f4max(a, b1), f4max(c, d));
    }
    __syncthreads();

    // Phase M16v: sA[i] = max(M4v[i], +4, +8, +12), i in [0,80).
    #pragma unroll 4
    for (int u = tid; u < 80 * V_C4; u += 256) {
        const int i  = u >> 5;
        const int c4 = u & 31;
        float4 a = *(const float4*)(sB + (i     ) * SV + 4 * c4);
        float4 b1 = *(const float4*)(sB + (i +  4) * SV + 4 * c4);
        float4 c = *(const float4*)(sB + (i +  8) * SV + 4 * c4);
        float4 d = *(const float4*)(sB + (i + 12) * SV + 4 * c4);
        *(float4*)(sA + i * SV + 4 * c4) = f4max(f4max(a, b1), f4max(c, d));
    }
    __syncthreads();

    // Phase out: out[j] = max(M16v[j], M16v[j+16], M4v[j+31]); write tmp.
    #pragma unroll 4
    for (int u = tid; u < V_TH * V_C4; u += 256) {
        const int j  = u >> 5;
        const int c4 = u & 31;
        float4 a = *(const float4*)(sA + (j     ) * SV + 4 * c4);
        float4 b1 = *(const float4*)(sA + (j + 16) * SV + 4 * c4);
        float4 c = *(const float4*)(sB + (j + 31) * SV + 4 * c4);
        float4 v = f4max(f4max(a, b1), c);
        *(float4*)(tmp + ((size_t)b * H + r0 + j) * W + c0 + 4 * c4) = v;
    }
}

// --------------------------------------------------------------------------
// hpass: horizontal 35-window max + block partial sum.
// Grid (W/128, H/32, B) = (4,16,16), block 256. Static smem ~45 KB.
// --------------------------------------------------------------------------
__global__ void hpass(const float* __restrict__ tmp, float* __restrict__ part) {
    __shared__ float sA[H_TR * SH];   // raw -> later M16h
    __shared__ float sB[H_TR * SH];   // M4h
    __shared__ float red[256];

    const int tid = threadIdx.y * 32 + threadIdx.x;
    const int b = blockIdx.z;
    const int rt = blockIdx.y;
    const int c0 = blockIdx.x * H_OC;
    const int lb = c0 - 20;           // aligned load base (168 cols)

    // Phase L: 32 rows x 42 float4, per-component pad outside [0,W).
    #pragma unroll 4
    for (int u = tid; u < H_TR * H_LC4; u += 256) {
        const int r  = u / H_LC4;
        const int c4 = u - r * H_LC4;
        const int gr = rt * H_TR + r;
        const int gc0 = lb + 4 * c4;
        const float* rowp = tmp + ((size_t)b * H + gr) * W;
        float4 v;
        if (gc0 >= 0 && gc0 + 3 < W) {
            v = *(const float4*)(rowp + gc0);
        } else {
            float t[4];
            #pragma unroll
            for (int k = 0; k < 4; k++) {
                int gc = gc0 + k;
                t[k] = (gc >= 0 && gc < W) ? rowp[gc] : NEG_BIG;
            }
            v = make_float4(t[0], t[1], t[2], t[3]);
        }
        *(float4*)(sA + r * SH + 4 * c4) = v;
    }
    __syncthreads();

    // Phase M4h: out cols 0..163 (41 float4). out[c]=max(s[c..c+3]).
    #pragma unroll 4
    for (int u = tid; u < H_TR * 41; u += 256) {
        const int r  = u / 41;
        const int c4 = u - r * 41;
        float4 a = *(const float4*)(sA + r * SH + 4 * c4);
        float4 bb = *(const float4*)(sA + r * SH + 4 * c4 + 4);
        float4 o;
        o.x = fmaxf(fmaxf(a.x, a.y), fmaxf(a.z, a.w));
        o.y = fmaxf(fmaxf(a.y, a.z), fmaxf(a.w, bb.x));
        o.z = fmaxf(fmaxf(a.z, a.w), fmaxf(bb.x, bb.y));
        o.w = fmaxf(fmaxf(a.w, bb.x), fmaxf(bb.y, bb.z));
        *(float4*)(sB + r * SH + 4 * c4) = o;
    }
    __syncthreads();

    // Phase M16h: out cols 0..147 (37 float4). out[c]=max(M4h[c],+4,+8,+12).
    #pragma unroll 4
    for (int u = tid; u < H_TR * 37; u += 256) {
        const int r  = u / 37;
        const int c4 = u - r * 37;
        float4 a = *(const float4*)(sB + r * SH + 4 * c4);
        float4 b1 = *(const float4*)(sB + r * SH + 4 * c4 + 4);
        float4 c = *(const float4*)(sB + r * SH + 4 * c4 + 8);
        float4 d = *(const float4*)(sB + r * SH + 4 * c4 + 12);
        *(float4*)(sA + r * SH + 4 * c4) = f4max(f4max(a, b1), f4max(c, d));
    }
    __syncthreads();

    // Phase final: dc[j] = max(M16h[j+3], M16h[j+19], M4h[j+34]); accumulate.
    float acc = 0.0f;
    #pragma unroll 4
    for (int u = tid; u < H_TR * H_OC; u += 256) {
        const int r = u >> 7;
        const int j = u & 127;
        float m = fmaxf(fmaxf(sA[r * SH + j + 3], sA[r * SH + j + 19]),
                        sB[r * SH + j + 34]);
        acc += m;
    }

    red[tid] = acc;
    __syncthreads();
    for (int s = 128; s > 0; s >>= 1) {
        if (tid < s) red[tid] += red[tid + s];
        __syncthreads();
    }
    if (tid == 0) {
        int bi = (b * gridDim.y + rt) * gridDim.x + blockIdx.x;
        part[bi] = red[0];
    }
}

// --------------------------------------------------------------------------
// final reduce: 1024 partials -> -mean (double accum).
// --------------------------------------------------------------------------
__global__ void final_reduce(const float* __restrict__ part, float* __restrict__ out) {
    __shared__ double red[256];
    const int tid = threadIdx.x;
    const int NPART = B * (H / H_TR) * (W / H_OC);
    double acc = 0.0;
    for (int i = tid; i < NPART; i += 256) acc += (double)part[i];
    red[tid] = acc;
    __syncthreads();
    for (int s = 128; s > 0; s >>= 1) {
        if (tid < s) red[tid] += red[tid + s];
        __syncthreads();
    }
    if (tid == 0) {
        double n = (double)B * H * W;
        out[0] = (float)(-(red[0] / n));
    }
}

extern "C" void kernel_launch(void* const* d_in, const int* in_sizes, int n_in,
                              void* d_out, int out_size) {
    const float* x = (const float*)d_in[0];
    float* out = (float*)d_out;

    float* tmp;
    float* part;
    cudaGetSymbolAddress((void**)&tmp, g_tmp);
    cudaGetSymbolAddress((void**)&part, g_part);

    const int vsmem = (V_ROWS + (V_ROWS - 3)) * SV * (int)sizeof(float); // ~101.9 KB
    cudaFuncSetAttribute(vpass, cudaFuncAttributeMaxDynamicSharedMemorySize, vsmem);

    dim3 blk(32, 8);
    dim3 vgrd(W / (V_C4 * 4), H / V_TH, B);    // (4, 8, 16)
    vpass<<<vgrd, blk, vsmem>>>(x, tmp);

    dim3 hgrd(W / H_OC, H / H_TR, B);          // (4, 16, 16)
    hpass<<<hgrd, blk>>>(tmp, part);

    final_reduce<<<1, 256>>>(part, out);
}

// round 5
// speedup vs baseline: 1.4913x; 1.1231x over previous
#include <cuda_runtime.h>
#include <cstddef>

// x: [B=16, C=3, H=512, W=512] float32; patch=35, pad=17.
#define B 16
#define H 512
#define W 512
#define HALO 17

#define NEG_BIG (-1e30f)

// ---------------- vpass tiling (64 rows x 64 cols out) ----------------
#define V_TH 64                       // output rows / tile
#define V_ROWS (V_TH + 2 * HALO)      // 98 loaded rows
#define V_C4 16                       // float4 cols / tile (=64 cols)
#define SV 68                         // shared row stride in floats (17 float4)
// smem: sA raw (98 rows) + sB M4 (95 rows) = 52.5 KB -> 4 CTAs/SM

// ---------------- hpass tiling ----------------
#define H_TR 32                       // rows / tile
#define H_OC 128                      // output cols / tile
#define H_LC4 42                      // loaded float4 cols (168 cols, lb = c0-20)
#define SH 172                        // shared row stride in floats

__device__ float g_tmp[(size_t)B * H * W];
__device__ float g_part[B * (H / H_TR) * (W / H_OC)];   // 1024 partials

__device__ __forceinline__ float4 f4max(float4 a, float4 b) {
    return make_float4(fmaxf(a.x, b.x), fmaxf(a.y, b.y),
                       fmaxf(a.z, b.z), fmaxf(a.w, b.w));
}

// --------------------------------------------------------------------------
// vpass: channel max of (1-x) fused with vertical 35-window max.
// Grid (W/64, H/64, B) = (8,8,16) = 1024 CTAs, block 256, 52.5 KB dyn smem.
// --------------------------------------------------------------------------
__global__ void __launch_bounds__(256, 4)
vpass(const float* __restrict__ x, float* __restrict__ tmp) {
    extern __shared__ float smem[];
    float* sA = smem;                     // raw rows (98)
    float* sB = smem + V_ROWS * SV;       // M4 rows (95)

    const int tid = threadIdx.y * 32 + threadIdx.x;
    const int b   = blockIdx.z;
    const int r0  = blockIdx.y * V_TH;
    const int c0  = blockIdx.x * (V_C4 * 4);

    const float* xb = x + (size_t)b * 3 * H * W;

    // Phase L: 98 rows x 16 float4, fused v = 1 - min_c(x).
    #pragma unroll 4
    for (int u = tid; u < V_ROWS * V_C4; u += 256) {
        const int i  = u >> 4;
        const int c4 = u & 15;
        const int gr = r0 - HALO + i;
        float4 v;
        if (gr >= 0 && gr < H) {
            const float* p = xb + (size_t)gr * W + c0 + 4 * c4;
            float4 a0 = *(const float4*)p;
            float4 a1 = *(const float4*)(p + (size_t)H * W);
            float4 a2 = *(const float4*)(p + 2 * (size_t)H * W);
            v.x = 1.0f - fminf(a0.x, fminf(a1.x, a2.x));
            v.y = 1.0f - fminf(a0.y, fminf(a1.y, a2.y));
            v.z = 1.0f - fminf(a0.z, fminf(a1.z, a2.z));
            v.w = 1.0f - fminf(a0.w, fminf(a1.w, a2.w));
        } else {
            v = make_float4(NEG_BIG, NEG_BIG, NEG_BIG, NEG_BIG);
        }
        *(float4*)(sA + i * SV + 4 * c4) = v;
    }
    __syncthreads();

    // Phase M4: sB[i] = max(rows i..i+3), i in [0,95).
    #pragma unroll 4
    for (int u = tid; u < (V_ROWS - 3) * V_C4; u += 256) {
        const int i  = u >> 4;
        const int c4 = u & 15;
        float4 a  = *(const float4*)(sA + (i    ) * SV + 4 * c4);
        float4 b1 = *(const float4*)(sA + (i + 1) * SV + 4 * c4);
        float4 c  = *(const float4*)(sA + (i + 2) * SV + 4 * c4);
        float4 d  = *(const float4*)(sA + (i + 3) * SV + 4 * c4);
        *(float4*)(sB + i * SV + 4 * c4) = f4max(f4max(a, b1), f4max(c, d));
    }
    __syncthreads();

    // Phase out: out[j] = max(M4[j+4k] k=0..7, M4[j+31])  (covers [j, j+34]).
    #pragma unroll 4
    for (int u = tid; u < V_TH * V_C4; u += 256) {
        const int j  = u >> 4;
        const int c4 = u & 15;
        const float* base = sB + j * SV + 4 * c4;
        float4 m = *(const float4*)(base);
        m = f4max(m, *(const float4*)(base +  4 * SV));
        m = f4max(m, *(const float4*)(base +  8 * SV));
        m = f4max(m, *(const float4*)(base + 12 * SV));
        m = f4max(m, *(const float4*)(base + 16 * SV));
        m = f4max(m, *(const float4*)(base + 20 * SV));
        m = f4max(m, *(const float4*)(base + 24 * SV));
        m = f4max(m, *(const float4*)(base + 28 * SV));
        m = f4max(m, *(const float4*)(base + 31 * SV));
        *(float4*)(tmp + ((size_t)b * H + r0 + j) * W + c0 + 4 * c4) = m;
    }
}

// --------------------------------------------------------------------------
// hpass: horizontal 35-window max + block partial sum.
// Grid (W/128, H/32, B) = (4,16,16), block 256.
// --------------------------------------------------------------------------
__global__ void __launch_bounds__(256)
hpass(const float* __restrict__ tmp, float* __restrict__ part) {
    __shared__ float sA[H_TR * SH];   // raw -> later M16h
    __shared__ float sB[H_TR * SH];   // M4h
    __shared__ float red[256];

    const int tid = threadIdx.y * 32 + threadIdx.x;
    const int b = blockIdx.z;
    const int rt = blockIdx.y;
    const int c0 = blockIdx.x * H_OC;
    const int lb = c0 - 20;           // aligned load base (168 cols)

    // Phase L: 32 rows x 42 float4, per-component pad outside [0,W).
    #pragma unroll 4
    for (int u = tid; u < H_TR * H_LC4; u += 256) {
        const int r  = u / H_LC4;
        const int c4 = u - r * H_LC4;
        const int gr = rt * H_TR + r;
        const int gc0 = lb + 4 * c4;
        const float* rowp = tmp + ((size_t)b * H + gr) * W;
        float4 v;
        if (gc0 >= 0 && gc0 + 3 < W) {
            v = *(const float4*)(rowp + gc0);
        } else {
            float t[4];
            #pragma unroll
            for (int k = 0; k < 4; k++) {
                int gc = gc0 + k;
                t[k] = (gc >= 0 && gc < W) ? rowp[gc] : NEG_BIG;
            }
            v = make_float4(t[0], t[1], t[2], t[3]);
        }
        *(float4*)(sA + r * SH + 4 * c4) = v;
    }
    __syncthreads();

    // Phase M4h: out cols 0..163 (41 float4). out[c]=max(s[c..c+3]).
    #pragma unroll 4
    for (int u = tid; u < H_TR * 41; u += 256) {
        const int r  = u / 41;
        const int c4 = u - r * 41;
        float4 a  = *(const float4*)(sA + r * SH + 4 * c4);
        float4 bb = *(const float4*)(sA + r * SH + 4 * c4 + 4);
        float4 o;
        o.x = fmaxf(fmaxf(a.x, a.y), fmaxf(a.z, a.w));
        o.y = fmaxf(fmaxf(a.y, a.z), fmaxf(a.w, bb.x));
        o.z = fmaxf(fmaxf(a.z, a.w), fmaxf(bb.x, bb.y));
        o.w = fmaxf(fmaxf(a.w, bb.x), fmaxf(bb.y, bb.z));
        *(float4*)(sB + r * SH + 4 * c4) = o;
    }
    __syncthreads();

    // Phase M16h: out cols 0..147 (37 float4). out[c]=max(M4h[c],+4,+8,+12).
    #pragma unroll 4
    for (int u = tid; u < H_TR * 37; u += 256) {
        const int r  = u / 37;
        const int c4 = u - r * 37;
        float4 a  = *(const float4*)(sB + r * SH + 4 * c4);
        float4 b1 = *(const float4*)(sB + r * SH + 4 * c4 + 4);
        float4 c  = *(const float4*)(sB + r * SH + 4 * c4 + 8);
        float4 d  = *(const float4*)(sB + r * SH + 4 * c4 + 12);
        *(float4*)(sA + r * SH + 4 * c4) = f4max(f4max(a, b1), f4max(c, d));
    }
    __syncthreads();

    // Phase final: dc[j] = max(M16h[j+3], M16h[j+19], M4h[j+34]); accumulate.
    float acc = 0.0f;
    #pragma unroll 4
    for (int u = tid; u < H_TR * H_OC; u += 256) {
        const int r = u >> 7;
        const int j = u & 127;
        float m = fmaxf(fmaxf(sA[r * SH + j + 3], sA[r * SH + j + 19]),
                        sB[r * SH + j + 34]);
        acc += m;
    }

    red[tid] = acc;
    __syncthreads();
    for (int s = 128; s > 0; s >>= 1) {
        if (tid < s) red[tid] += red[tid + s];
        __syncthreads();
    }
    if (tid == 0) {
        int bi = (b * gridDim.y + rt) * gridDim.x + blockIdx.x;
        part[bi] = red[0];
    }
}

// --------------------------------------------------------------------------
// final reduce: 1024 partials -> -mean (double accum).
// --------------------------------------------------------------------------
__global__ void final_reduce(const float* __restrict__ part, float* __restrict__ out) {
    __shared__ double red[256];
    const int tid = threadIdx.x;
    const int NPART = B * (H / H_TR) * (W / H_OC);
    double acc = 0.0;
    for (int i = tid; i < NPART; i += 256) acc += (double)part[i];
    red[tid] = acc;
    __syncthreads();
    for (int s = 128; s > 0; s >>= 1) {
        if (tid < s) red[tid] += red[tid + s];
        __syncthreads();
    }
    if (tid == 0) {
        double n = (double)B * H * W;
        out[0] = (float)(-(red[0] / n));
    }
}

extern "C" void kernel_launch(void* const* d_in, const int* in_sizes, int n_in,
                              void* d_out, int out_size) {
    const float* x = (const float*)d_in[0];
    float* out = (float*)d_out;

    float* tmp;
    float* part;
    cudaGetSymbolAddress((void**)&tmp, g_tmp);
    cudaGetSymbolAddress((void**)&part, g_part);

    const int vsmem = (V_ROWS + (V_ROWS - 3)) * SV * (int)sizeof(float); // 52.5 KB
    cudaFuncSetAttribute(vpass, cudaFuncAttributeMaxDynamicSharedMemorySize, vsmem);

    dim3 blk(32, 8);
    dim3 vgrd(W / (V_C4 * 4), H / V_TH, B);    // (8, 8, 16)
    vpass<<<vgrd, blk, vsmem>>>(x, tmp);

    dim3 hgrd(W / H_OC, H / H_TR, B);          // (4, 16, 16)
    hpass<<<hgrd, blk>>>(tmp, part);

    final_reduce<<<1, 256>>>(part, out);
}

// round 7
// speedup vs baseline: 1.8269x; 1.2250x over previous
#include <cuda_runtime.h>
#include <cstddef>

// x: [B=16, C=3, H=512, W=512] float32; patch=35, pad=17.
#define B 16
#define H 512
#define W 512
#define HALO 17
#define NEG_BIG (-1e30f)

// ---- vpass: tile 64 out rows x 64 cols, 98 raw rows, 1 smem buffer ----
#define V_TH 64
#define V_ROWS 98
#define V_C4 16
#define SV 68                          // shared row stride (floats)

// ---- hpass: tile 32 rows x 128 out cols, 168 loaded cols ----
#define H_TR 32
#define H_OC 128
#define H_LC4 42                       // 168 cols loaded, base = c0-20
#define SH 172                         // shared row stride (floats)

__device__ float g_tmp[(size_t)B * H * W];
__device__ float g_part[B * (H / H_TR) * (W / H_OC)];   // 1024 partials

__device__ __forceinline__ float4 f4max(float4 a, float4 b) {
    return make_float4(fmaxf(a.x, b.x), fmaxf(a.y, b.y),
                       fmaxf(a.z, b.z), fmaxf(a.w, b.w));
}

// --------------------------------------------------------------------------
// vpass: channel max of (1-x) fused with vertical 35-window max.
// Grid (8, 8, 16) = 1024 CTAs, 128 threads, 26.7 KB static smem, 8 CTA/SM.
// Phase out: thread (c4, rb) produces output rows 8rb..8rb+7 at f4-col c4.
//   out[k] window = raw rows [8rb+k, 8rb+k+34].
//   C = max(raw[8rb+7 .. 8rb+34]); D[k]=max(raw[8rb+k..8rb+6]);
//   U[k]=max(raw[8rb+35..8rb+34+k]); out[k]=max(D[k],C,U[k]).
// --------------------------------------------------------------------------
__global__ void __launch_bounds__(128, 8)
vpass(const float* __restrict__ x, float* __restrict__ tmp) {
    __shared__ float sraw[V_ROWS * SV];

    const int tid = threadIdx.x;
    const int b   = blockIdx.z;
    const int r0  = blockIdx.y * V_TH;
    const int c0  = blockIdx.x * (V_C4 * 4);
    const float* xb = x + (size_t)b * 3 * H * W;

    // Phase L: 98 rows x 16 float4, fused v = 1 - min_c(x).
    #pragma unroll 4
    for (int u = tid; u < V_ROWS * V_C4; u += 128) {
        const int i  = u >> 4;
        const int c4 = u & 15;
        const int gr = r0 - HALO + i;
        float4 v;
        if (gr >= 0 && gr < H) {
            const float* p = xb + (size_t)gr * W + c0 + 4 * c4;
            float4 a0 = *(const float4*)p;
            float4 a1 = *(const float4*)(p + (size_t)H * W);
            float4 a2 = *(const float4*)(p + 2 * (size_t)H * W);
            v.x = 1.0f - fminf(a0.x, fminf(a1.x, a2.x));
            v.y = 1.0f - fminf(a0.y, fminf(a1.y, a2.y));
            v.z = 1.0f - fminf(a0.z, fminf(a1.z, a2.z));
            v.w = 1.0f - fminf(a0.w, fminf(a1.w, a2.w));
        } else {
            v = make_float4(NEG_BIG, NEG_BIG, NEG_BIG, NEG_BIG);
        }
        *(float4*)(sraw + i * SV + 4 * c4) = v;
    }
    __syncthreads();

    // Phase out.
    const int c4 = tid & 15;
    const int rb = tid >> 4;                 // 0..7
    const float* base = sraw + (rb * 8) * SV + 4 * c4;

    // C = max rows 7..34 (relative).
    float4 C = *(const float4*)(base + 7 * SV);
    #pragma unroll
    for (int r = 8; r <= 34; r++)
        C = f4max(C, *(const float4*)(base + r * SV));

    // P[k] = max(D[k], C); D[k] = max rows k..6.
    float4 P[8];
    P[7] = C;
    {
        float4 d = *(const float4*)(base + 6 * SV);
        P[6] = f4max(d, C);
        #pragma unroll
        for (int k = 5; k >= 0; k--) {
            d = f4max(d, *(const float4*)(base + k * SV));
            P[k] = f4max(d, C);
        }
    }

    // Ascending U + stores. out row = r0 + rb*8 + k.
    float* outp = tmp + ((size_t)b * H + r0 + rb * 8) * W + c0 + 4 * c4;
    *(float4*)outp = P[0];
    {
        float4 u = *(const float4*)(base + 35 * SV);
        *(float4*)(outp + W) = f4max(P[1], u);
        #pragma unroll
        for (int k = 2; k <= 7; k++) {
            u = f4max(u, *(const float4*)(base + (34 + k) * SV));
            *(float4*)(outp + (size_t)k * W) = f4max(P[k], u);
        }
    }
}

// --------------------------------------------------------------------------
// hpass: horizontal 35-window max + partial sum.
// Grid (4, 16, 16) = 1024 CTAs, 128 threads, ~22.5 KB smem, 8 CTA/SM.
// Thread (g, rb): output cols 8g..8g+7 for rows rb+8it (it=0..3).
//   Register window a[0..47] = smem cols 8g..8g+47 (12 float4 loads).
//   out[k] window = a[3+k .. 37+k]. C=max(a[10..37]); D over a[3+k..9];
//   U over a[38..37+k]. dc >= 0 so |dc| = dc; accumulate.
// --------------------------------------------------------------------------
__global__ void __launch_bounds__(128, 8)
hpass(const float* __restrict__ tmp, float* __restrict__ part) {
    __shared__ float sraw[H_TR * SH];
    __shared__ float red[128];

    const int tid = threadIdx.x;
    const int b  = blockIdx.z;
    const int rt = blockIdx.y;
    const int c0 = blockIdx.x * H_OC;
    const int lb = c0 - 20;

    // Phase L: 32 rows x 42 float4, per-component pad outside [0,W).
    #pragma unroll 4
    for (int u = tid; u < H_TR * H_LC4; u += 128) {
        const int r  = u / H_LC4;
        const int c4 = u - r * H_LC4;
        const int gr = rt * H_TR + r;
        const int gc0 = lb + 4 * c4;
        const float* rowp = tmp + ((size_t)b * H + gr) * W;
        float4 v;
        if (gc0 >= 0 && gc0 + 3 < W) {
            v = *(const float4*)(rowp + gc0);
        } else {
            float t[4];
            #pragma unroll
            for (int k = 0; k < 4; k++) {
                int gc = gc0 + k;
                t[k] = (gc >= 0 && gc < W) ? rowp[gc] : NEG_BIG;
            }
            v = make_float4(t[0], t[1], t[2], t[3]);
        }
        *(float4*)(sraw + r * SH + 4 * c4) = v;
    }
    __syncthreads();

    const int g  = tid & 15;
    const int rb = tid >> 4;
    float acc = 0.0f;

    #pragma unroll
    for (int it = 0; it < 4; it++) {
        const int r = rb + 8 * it;
        const float* row = sraw + r * SH + 8 * g;

        float a[48];
        #pragma unroll
        for (int i = 0; i < 12; i++) {
            float4 v = *(const float4*)(row + 4 * i);
            a[4 * i + 0] = v.x; a[4 * i + 1] = v.y;
            a[4 * i + 2] = v.z; a[4 * i + 3] = v.w;
        }

        float C = a[10];
        #pragma unroll
        for (int i = 11; i <= 37; i++) C = fmaxf(C, a[i]);

        float P[8];
        P[7] = C;
        {
            float d = a[9];
            P[6] = fmaxf(d, C);
            #pragma unroll
            for (int k = 5; k >= 0; k--) {
                d = fmaxf(d, a[3 + k]);
                P[k] = fmaxf(d, C);
            }
        }

        acc += P[0];
        {
            float u = a[38];
            acc += fmaxf(P[1], u);
            #pragma unroll
            for (int k = 2; k <= 7; k++) {
                u = fmaxf(u, a[37 + k]);
                acc += fmaxf(P[k], u);
            }
        }
    }

    red[tid] = acc;
    __syncthreads();
    for (int s = 64; s > 0; s >>= 1) {
        if (tid < s) red[tid] += red[tid + s];
        __syncthreads();
    }
    if (tid == 0) {
        int bi = (b * gridDim.y + rt) * gridDim.x + blockIdx.x;
        part[bi] = red[0];
    }
}

// --------------------------------------------------------------------------
// final reduce: 1024 partials -> -mean (double accum).
// --------------------------------------------------------------------------
__global__ void final_reduce(const float* __restrict__ part, float* __restrict__ out) {
    __shared__ double red[256];
    const int tid = threadIdx.x;
    const int NPART = B * (H / H_TR) * (W / H_OC);
    double acc = 0.0;
    for (int i = tid; i < NPART; i += 256) acc += (double)part[i];
    red[tid] = acc;
    __syncthreads();
    for (int s = 128; s > 0; s >>= 1) {
        if (tid < s) red[tid] += red[tid + s];
        __syncthreads();
    }
    if (tid == 0) {
        double n = (double)B * H * W;
        out[0] = (float)(-(red[0] / n));
    }
}

extern "C" void kernel_launch(void* const* d_in, const int* in_sizes, int n_in,
                              void* d_out, int out_size) {
    const float* x = (const float*)d_in[0];
    float* out = (float*)d_out;

    float* tmp;
    float* part;
    cudaGetSymbolAddress((void**)&tmp, g_tmp);
    cudaGetSymbolAddress((void**)&part, g_part);

    vpass<<<dim3(W / (V_C4 * 4), H / V_TH, B), 128>>>(x, tmp);      // (8,8,16)
    hpass<<<dim3(W / H_OC, H / H_TR, B), 128>>>(tmp, part);         // (4,16,16)
    final_reduce<<<1, 256>>>(part, out);
}